// round 14
// baseline (speedup 1.0000x reference)
#include <cuda_runtime.h>
#include <cuda_bf16.h>
#include <math.h>
#include <stdint.h>

#define NTOK 16384
#define DDIM 2048
#define NEXP 64
#define TOPK 8

// output layout (floats)
#define OFF_TOP   0            // 16384*8
#define OFF_SC    131072       // 16384*64
#define OFF_IDX   1179648      // 16384*8
#define OFF_HIST  1310720      // 64
#define OFF_ENT   1310784      // 1

#define BM 64                  // tokens per CTA
#define BK 32                  // k per tile
#define NT (DDIM / BK)         // 64 iterations
#define THREADS 256

// smem: A[2][3][64 rows][80B]  then  B[2][3][64 rows][80B]
#define ROWB       80          // padded row stride in bytes (40 bf16)
#define TERM_BYTES (64 * ROWB) // 5120
#define BUF_BYTES  (3 * TERM_BYTES)
#define BREGION    (2 * BUF_BYTES)
#define DSMEM_BYTES (4 * BUF_BYTES + 128)

// pre-split gate weights: [term][expert][k] bf16
__device__ __align__(16) __nv_bfloat16 g_wb[3 * NEXP * DDIM];

// ---------------- helpers ----------------
__device__ __forceinline__ uint32_t smem_u32(const void* p) {
    uint32_t a;
    asm("{ .reg .u64 t; cvta.to.shared.u64 t, %1; cvt.u32.u64 %0, t; }" : "=r"(a) : "l"(p));
    return a;
}
__device__ __forceinline__ void cp_async16(uint32_t dst, const void* src) {
    asm volatile("cp.async.cg.shared.global [%0], [%1], 16;" :: "r"(dst), "l"(src) : "memory");
}
// exact 3-term bf16 split of a float pair -> 3 packed bf16x2 (lo=a, hi=b)
__device__ __forceinline__ void split2(float a, float b,
                                       uint32_t& p0, uint32_t& p1, uint32_t& p2) {
    asm("cvt.rn.bf16x2.f32 %0, %1, %2;" : "=r"(p0) : "f"(b), "f"(a));
    float a0 = __uint_as_float(p0 << 16);
    float b0 = __uint_as_float(p0 & 0xFFFF0000u);
    float ra = a - a0, rb = b - b0;
    asm("cvt.rn.bf16x2.f32 %0, %1, %2;" : "=r"(p1) : "f"(rb), "f"(ra));
    float a1 = __uint_as_float(p1 << 16);
    float b1 = __uint_as_float(p1 & 0xFFFF0000u);
    ra -= a1; rb -= b1;
    asm("cvt.rn.bf16x2.f32 %0, %1, %2;" : "=r"(p2) : "f"(rb), "f"(ra));
}
__device__ __forceinline__ void ldsm4(uint32_t* r, uint32_t addr) {
    asm volatile("ldmatrix.sync.aligned.m8n8.x4.shared.b16 {%0,%1,%2,%3}, [%4];"
                 : "=r"(r[0]), "=r"(r[1]), "=r"(r[2]), "=r"(r[3]) : "r"(addr));
}
__device__ __forceinline__ void mma16816(float* c, const uint32_t* a, const uint32_t* b) {
    asm volatile(
        "mma.sync.aligned.m16n8k16.row.col.f32.bf16.bf16.f32 "
        "{%0,%1,%2,%3}, {%4,%5,%6,%7}, {%8,%9}, {%0,%1,%2,%3};"
        : "+f"(c[0]), "+f"(c[1]), "+f"(c[2]), "+f"(c[3])
        : "r"(a[0]), "r"(a[1]), "r"(a[2]), "r"(a[3]), "r"(b[0]), "r"(b[1]));
}

// ---------------- pre-kernel: W split + output tail zeroing ----------------
__global__ void wconv_kernel(const float* __restrict__ W, float* __restrict__ out) {
    int e = blockIdx.x;
    int k = threadIdx.x * 8;
    if (e == 0 && threadIdx.x < 65) out[OFF_HIST + threadIdx.x] = 0.0f;
    const float* src = W + (size_t)e * DDIM + k;
    float4 v0 = *(const float4*)(src);
    float4 v1 = *(const float4*)(src + 4);
    uint32_t t0[4], t1[4], t2[4];
    split2(v0.x, v0.y, t0[0], t1[0], t2[0]);
    split2(v0.z, v0.w, t0[1], t1[1], t2[1]);
    split2(v1.x, v1.y, t0[2], t1[2], t2[2]);
    split2(v1.z, v1.w, t0[3], t1[3], t2[3]);
    uint32_t* wb = (uint32_t*)g_wb;
    size_t base = ((size_t)e * DDIM + k) >> 1;
    size_t tstr = ((size_t)NEXP * DDIM) >> 1;
    *(uint4*)(wb + base)            = make_uint4(t0[0], t0[1], t0[2], t0[3]);
    *(uint4*)(wb + base + tstr)     = make_uint4(t1[0], t1[1], t1[2], t1[3]);
    *(uint4*)(wb + base + 2 * tstr) = make_uint4(t2[0], t2[1], t2[2], t2[3]);
}

// ---------------- main kernel ----------------
__global__ __launch_bounds__(THREADS, 2)
void router_mma_kernel(const float* __restrict__ x,
                       const float* __restrict__ bias,
                       float* __restrict__ out)
{
    extern __shared__ char dsm[];
    __shared__ float sbias[NEXP];
    __shared__ float shist[NEXP];

    const int tid  = threadIdx.x;
    const int lane = tid & 31;
    const int w    = tid >> 5;
    const int m0   = blockIdx.x * BM;

    const uint32_t SA = (smem_u32(dsm) + 127) & ~127u;
    #define AOFF(buf, term) (SA + (buf) * BUF_BYTES + (term) * TERM_BYTES)
    #define BOFF(buf, term) (SA + BREGION + (buf) * BUF_BYTES + (term) * TERM_BYTES)

    if (tid < NEXP) { sbias[tid] = bias[tid]; shist[tid] = 0.0f; }

    // warp tile: 16m x 32n; warps: 4 along m, 2 along n
    const int wm0 = (w >> 1) * 16;
    const int wn0 = (w & 1) * 32;

    // ldmatrix per-lane address components
    const int lj = lane >> 3, li = lane & 7;
    const int arow_l = (lj & 1) * 8 + li;
    const int akb    = (lj >> 1) * 16;
    const int brow_l = (lj >> 1) * 8 + li;
    const int bkb    = (lj & 1) * 16;

    // accM: main (0,0) product, current chunk; accT: flushed main total;
    // accC: corrections ONLY (stays small-magnitude all loop -> low rounding noise)
    float accM[4][4], accT[4][4], accC[4][4];
#pragma unroll
    for (int nt = 0; nt < 4; nt++)
#pragma unroll
        for (int r = 0; r < 4; r++) {
            accM[nt][r] = 0.0f; accT[nt][r] = 0.0f; accC[nt][r] = 0.0f;
        }

    // x staging: each thread handles 8 floats: row = tid>>2, koff = (tid&3)*8
    const int xrow  = tid >> 2;
    const int xkoff = (tid & 3) * 8;
    const float* xptr = x + (size_t)(m0 + xrow) * DDIM + xkoff;
    const uint32_t a_sts = xrow * ROWB + xkoff * 2;

    float4 xr[2];
    xr[0] = *(const float4*)(xptr);
    xr[1] = *(const float4*)(xptr + 4);

    auto split_store = [&](int buf) {
        uint32_t s0[4], s1[4], s2[4];
        split2(xr[0].x, xr[0].y, s0[0], s1[0], s2[0]);
        split2(xr[0].z, xr[0].w, s0[1], s1[1], s2[1]);
        split2(xr[1].x, xr[1].y, s0[2], s1[2], s2[2]);
        split2(xr[1].z, xr[1].w, s0[3], s1[3], s2[3]);
        asm volatile("st.shared.v4.b32 [%0], {%1,%2,%3,%4};"
                     :: "r"(AOFF(buf, 0) + a_sts), "r"(s0[0]), "r"(s0[1]), "r"(s0[2]), "r"(s0[3]) : "memory");
        asm volatile("st.shared.v4.b32 [%0], {%1,%2,%3,%4};"
                     :: "r"(AOFF(buf, 1) + a_sts), "r"(s1[0]), "r"(s1[1]), "r"(s1[2]), "r"(s1[3]) : "memory");
        asm volatile("st.shared.v4.b32 [%0], {%1,%2,%3,%4};"
                     :: "r"(AOFF(buf, 2) + a_sts), "r"(s2[0]), "r"(s2[1]), "r"(s2[2]), "r"(s2[3]) : "memory");
    };

    // B copy: 768 x 16B per tile, 3 per thread
    auto b_copy = [&](int buf, int t) {
#pragma unroll
        for (int i = 0; i < 3; i++) {
            int idx  = tid + i * 256;
            int term = idx >> 8;
            int e    = (idx >> 2) & 63;
            int q    = idx & 3;
            uint32_t dst = BOFF(buf, term) + e * ROWB + q * 16;
            const __nv_bfloat16* src = g_wb + ((size_t)term * NEXP + e) * DDIM + t * BK + q * 8;
            cp_async16(dst, src);
        }
        asm volatile("cp.async.commit_group;" ::: "memory");
    };

    // prologue: tile 0
    split_store(0);
    b_copy(0, 0);
    xr[0] = *(const float4*)(xptr + BK);
    xr[1] = *(const float4*)(xptr + BK + 4);

#pragma unroll 1
    for (int t = 0; t < NT; t++) {
        const int buf = t & 1;
        if (t + 1 < NT) {
            split_store(buf ^ 1);
            b_copy(buf ^ 1, t + 1);
            asm volatile("cp.async.wait_group 1;" ::: "memory");
        } else {
            asm volatile("cp.async.wait_group 0;" ::: "memory");
        }
        __syncthreads();

        if (t + 2 < NT) {
            const float* nx = xptr + (t + 2) * BK;
            xr[0] = *(const float4*)(nx);
            xr[1] = *(const float4*)(nx + 4);
        }

#pragma unroll
        for (int kk = 0; kk < 2; kk++) {
            // term 0 -> main product into accM
            uint32_t a0[4], b0[2][4];
            ldsm4(a0, AOFF(buf, 0) + (wm0 + arow_l) * ROWB + kk * 32 + akb);
#pragma unroll
            for (int h = 0; h < 2; h++)
                ldsm4(b0[h], BOFF(buf, 0) + (wn0 + h * 16 + brow_l) * ROWB + kk * 32 + bkb);
#pragma unroll
            for (int nt = 0; nt < 4; nt++)
                mma16816(accM[nt], a0, &b0[nt >> 1][(nt & 1) * 2]);

            // term 1 -> corrections (0,1),(1,0),(1,1)
            uint32_t a1[4], b1[2][4];
            ldsm4(a1, AOFF(buf, 1) + (wm0 + arow_l) * ROWB + kk * 32 + akb);
#pragma unroll
            for (int h = 0; h < 2; h++)
                ldsm4(b1[h], BOFF(buf, 1) + (wn0 + h * 16 + brow_l) * ROWB + kk * 32 + bkb);
#pragma unroll
            for (int nt = 0; nt < 4; nt++) {
                mma16816(accC[nt], a0, &b1[nt >> 1][(nt & 1) * 2]);
                mma16816(accC[nt], a1, &b0[nt >> 1][(nt & 1) * 2]);
                mma16816(accC[nt], a1, &b1[nt >> 1][(nt & 1) * 2]);
            }

            // term 2 -> corrections (0,2),(2,0)
            uint32_t a2[4], b2[2][4];
            ldsm4(a2, AOFF(buf, 2) + (wm0 + arow_l) * ROWB + kk * 32 + akb);
#pragma unroll
            for (int h = 0; h < 2; h++)
                ldsm4(b2[h], BOFF(buf, 2) + (wn0 + h * 16 + brow_l) * ROWB + kk * 32 + bkb);
#pragma unroll
            for (int nt = 0; nt < 4; nt++) {
                mma16816(accC[nt], a0, &b2[nt >> 1][(nt & 1) * 2]);
                mma16816(accC[nt], a2, &b0[nt >> 1][(nt & 1) * 2]);
            }
        }

        // chunk flush into the DEDICATED total accT (never touched by MMAs)
        if ((t & 15) == 15) {
#pragma unroll
            for (int nt = 0; nt < 4; nt++)
#pragma unroll
                for (int r = 0; r < 4; r++) {
                    accT[nt][r] += accM[nt][r];
                    accM[nt][r] = 0.0f;
                }
        }
        __syncthreads();
    }

    // ---------------- epilogue ----------------
    float* ScA = (float*)(dsm + (SA - smem_u32(dsm)));   // reuse tile smem
#pragma unroll
    for (int nt = 0; nt < 4; nt++)
#pragma unroll
        for (int h = 0; h < 2; h++) {
            int m = wm0 + h * 8 + (lane >> 2);
            int n = wn0 + nt * 8 + (lane & 3) * 2;
            float l0 = accT[nt][2*h]   + accC[nt][2*h];
            float l1 = accT[nt][2*h+1] + accC[nt][2*h+1];
            float v0 = 1.0f / (1.0f + expf(-l0));
            float v1 = 1.0f / (1.0f + expf(-l1));
            ScA[m * 65 + n]     = v0;
            ScA[m * 65 + n + 1] = v1;
            *(float2*)&out[OFF_SC + (size_t)(m0 + m) * NEXP + n] = make_float2(v0, v1);
        }
    __syncthreads();

    // per-token top-8 (threads 0..63), strict > scan => lowest index wins ties
    if (tid < 64) {
        const int tok = m0 + tid;
        const float* row = &ScA[tid * 65];
        unsigned long long used = 0ULL;
        float ps[TOPK]; int pidx[TOPK];
        float ssum = 0.0f;
        for (int k = 0; k < TOPK; k++) {
            float best = -INFINITY, bsc = 0.0f;
            int bi = 0;
#pragma unroll
            for (int e = 0; e < NEXP; e++) {
                float v = row[e] + sbias[e];
                if (!((used >> e) & 1ULL) && v > best) { best = v; bi = e; bsc = row[e]; }
            }
            used |= (1ULL << bi);
            ps[k] = bsc; pidx[k] = bi; ssum += bsc;
            atomicAdd(&shist[bi], 1.0f);
        }
        float inv = 1.0f / (ssum + 1e-20f);
        float ent = 0.0f;
#pragma unroll
        for (int k = 0; k < TOPK; k++) {
            float p = ps[k] * inv;             // ROUTE_SCALE == 1.0
            out[OFF_TOP + (size_t)tok * TOPK + k] = p;
            out[OFF_IDX + (size_t)tok * TOPK + k] = (float)pidx[k];
            ent += p * logf(p);
        }
        atomicAdd(&out[OFF_ENT], -ent * (1.0f / (float)NTOK));
    }
    __syncthreads();
    if (tid < NEXP) {
        float h = shist[tid];
        if (h != 0.0f) atomicAdd(&out[OFF_HIST + tid], h);
    }
}

extern "C" void kernel_launch(void* const* d_in, const int* in_sizes, int n_in,
                              void* d_out, int out_size) {
    const float* x    = (const float*)d_in[0];
    const float* W    = (const float*)d_in[1];
    const float* bias = (const float*)d_in[2];
    float* out = (float*)d_out;

    cudaFuncSetAttribute(router_mma_kernel,
                         cudaFuncAttributeMaxDynamicSharedMemorySize, DSMEM_BYTES);
    wconv_kernel<<<NEXP, 256>>>(W, out);
    router_mma_kernel<<<NTOK / BM, THREADS, DSMEM_BYTES>>>(x, bias, out);
}

// round 15
// speedup vs baseline: 1.2527x; 1.2527x over previous
#include <cuda_runtime.h>
#include <cuda_fp16.h>
#include <math.h>
#include <stdint.h>

#define NTOK 16384
#define DDIM 2048
#define NEXP 64
#define TOPK 8

// output layout (floats)
#define OFF_TOP   0            // 16384*8
#define OFF_SC    131072       // 16384*64
#define OFF_IDX   1179648      // 16384*8
#define OFF_HIST  1310720      // 64
#define OFF_ENT   1310784      // 1

#define BM 64                  // tokens per CTA
#define BK 32                  // k per tile
#define NT (DDIM / BK)         // 64 iterations
#define THREADS 256

// smem: A[2][2][64 rows][80B]  then  B[2][2][64 rows][80B]
#define ROWB       80          // padded row stride in bytes (40 fp16)
#define TERM_BYTES (64 * ROWB) // 5120
#define BUF_BYTES  (2 * TERM_BYTES)   // 10240
#define BREGION    (2 * BUF_BYTES)    // 20480
#define DSMEM_BYTES (4 * BUF_BYTES + 128)

#define RSCALE 1024.0f
#define RSCALE_INV (1.0f / 1024.0f)

// pre-split gate weights: [term][expert][k] fp16 (term1 scaled by 1024)
__device__ __align__(16) __half g_wh[2 * NEXP * DDIM];

// ---------------- helpers ----------------
__device__ __forceinline__ uint32_t smem_u32(const void* p) {
    uint32_t a;
    asm("{ .reg .u64 t; cvta.to.shared.u64 t, %1; cvt.u32.u64 %0, t; }" : "=r"(a) : "l"(p));
    return a;
}
__device__ __forceinline__ void cp_async16(uint32_t dst, const void* src) {
    asm volatile("cp.async.cg.shared.global [%0], [%1], 16;" :: "r"(dst), "l"(src) : "memory");
}
// fp16 2-term split of a float pair -> 2 packed f16x2 (lo=a, hi=b).
// term1 = (v - fp16(v)) * 1024 (exact: Sterbenz subtraction + exact pow2 mul)
__device__ __forceinline__ void split2h(float a, float b, uint32_t& p0, uint32_t& p1) {
    asm("cvt.rn.f16x2.f32 %0, %1, %2;" : "=r"(p0) : "f"(b), "f"(a));
    __half2 h = *reinterpret_cast<__half2*>(&p0);
    float a0 = __low2float(h), b0 = __high2float(h);
    float ra = (a - a0) * RSCALE;
    float rb = (b - b0) * RSCALE;
    asm("cvt.rn.f16x2.f32 %0, %1, %2;" : "=r"(p1) : "f"(rb), "f"(ra));
}
__device__ __forceinline__ void ldsm4(uint32_t* r, uint32_t addr) {
    asm volatile("ldmatrix.sync.aligned.m8n8.x4.shared.b16 {%0,%1,%2,%3}, [%4];"
                 : "=r"(r[0]), "=r"(r[1]), "=r"(r[2]), "=r"(r[3]) : "r"(addr));
}
__device__ __forceinline__ void mma16816(float* c, const uint32_t* a, const uint32_t* b) {
    asm volatile(
        "mma.sync.aligned.m16n8k16.row.col.f32.f16.f16.f32 "
        "{%0,%1,%2,%3}, {%4,%5,%6,%7}, {%8,%9}, {%0,%1,%2,%3};"
        : "+f"(c[0]), "+f"(c[1]), "+f"(c[2]), "+f"(c[3])
        : "r"(a[0]), "r"(a[1]), "r"(a[2]), "r"(a[3]), "r"(b[0]), "r"(b[1]));
}

// ---------------- pre-kernel: W split + output tail zeroing ----------------
__global__ void wconv_kernel(const float* __restrict__ W, float* __restrict__ out) {
    int e = blockIdx.x;
    int k = threadIdx.x * 8;
    if (e == 0 && threadIdx.x < 65) out[OFF_HIST + threadIdx.x] = 0.0f;
    const float* src = W + (size_t)e * DDIM + k;
    float4 v0 = *(const float4*)(src);
    float4 v1 = *(const float4*)(src + 4);
    uint32_t t0[4], t1[4];
    split2h(v0.x, v0.y, t0[0], t1[0]);
    split2h(v0.z, v0.w, t0[1], t1[1]);
    split2h(v1.x, v1.y, t0[2], t1[2]);
    split2h(v1.z, v1.w, t0[3], t1[3]);
    uint32_t* wh = (uint32_t*)g_wh;
    size_t base = ((size_t)e * DDIM + k) >> 1;       // u32 index
    size_t tstr = ((size_t)NEXP * DDIM) >> 1;
    *(uint4*)(wh + base)        = make_uint4(t0[0], t0[1], t0[2], t0[3]);
    *(uint4*)(wh + base + tstr) = make_uint4(t1[0], t1[1], t1[2], t1[3]);
}

// ---------------- main kernel ----------------
__global__ __launch_bounds__(THREADS, 2)
void router_mma_kernel(const float* __restrict__ x,
                       const float* __restrict__ bias,
                       float* __restrict__ out)
{
    extern __shared__ char dsm[];
    __shared__ float sbias[NEXP];
    __shared__ float shist[NEXP];

    const int tid  = threadIdx.x;
    const int lane = tid & 31;
    const int w    = tid >> 5;
    const int m0   = blockIdx.x * BM;

    const uint32_t SA = (smem_u32(dsm) + 127) & ~127u;
    #define AOFF(buf, term) (SA + (buf) * BUF_BYTES + (term) * TERM_BYTES)
    #define BOFF(buf, term) (SA + BREGION + (buf) * BUF_BYTES + (term) * TERM_BYTES)

    if (tid < NEXP) { sbias[tid] = bias[tid]; shist[tid] = 0.0f; }

    // warp tile: 16m x 32n; warps: 4 along m, 2 along n
    const int wm0 = (w >> 1) * 16;
    const int wn0 = (w & 1) * 32;

    // ldmatrix per-lane address components
    const int lj = lane >> 3, li = lane & 7;
    const int arow_l = (lj & 1) * 8 + li;
    const int akb    = (lj >> 1) * 16;
    const int brow_l = (lj >> 1) * 8 + li;
    const int bkb    = (lj & 1) * 16;

    // accM: main (0,0) chunk; accT: flushed main total (never an MMA target);
    // accC: cross corrections, both scaled 2^10 -> one accumulator
    float accM[4][4], accT[4][4], accC[4][4];
#pragma unroll
    for (int nt = 0; nt < 4; nt++)
#pragma unroll
        for (int r = 0; r < 4; r++) {
            accM[nt][r] = 0.0f; accT[nt][r] = 0.0f; accC[nt][r] = 0.0f;
        }

    // x staging: each thread handles 8 floats: row = tid>>2, koff = (tid&3)*8
    const int xrow  = tid >> 2;
    const int xkoff = (tid & 3) * 8;
    const float* xptr = x + (size_t)(m0 + xrow) * DDIM + xkoff;
    const uint32_t a_sts = xrow * ROWB + xkoff * 2;

    // B copy invariants: chunk i covers term i; e,q identical for both i
    const int be = (tid >> 2) & 63;
    const int bq = tid & 3;
    const uint32_t b_dst = be * ROWB + bq * 16;
    const __half* bsrc0 = g_wh + (size_t)be * DDIM + bq * 8;
    const __half* bsrc1 = bsrc0 + (size_t)NEXP * DDIM;

    float4 xr[2];
    xr[0] = *(const float4*)(xptr);
    xr[1] = *(const float4*)(xptr + 4);

    auto split_store = [&](int buf) {
        uint32_t s0[4], s1[4];
        split2h(xr[0].x, xr[0].y, s0[0], s1[0]);
        split2h(xr[0].z, xr[0].w, s0[1], s1[1]);
        split2h(xr[1].x, xr[1].y, s0[2], s1[2]);
        split2h(xr[1].z, xr[1].w, s0[3], s1[3]);
        asm volatile("st.shared.v4.b32 [%0], {%1,%2,%3,%4};"
                     :: "r"(AOFF(buf, 0) + a_sts), "r"(s0[0]), "r"(s0[1]), "r"(s0[2]), "r"(s0[3]) : "memory");
        asm volatile("st.shared.v4.b32 [%0], {%1,%2,%3,%4};"
                     :: "r"(AOFF(buf, 1) + a_sts), "r"(s1[0]), "r"(s1[1]), "r"(s1[2]), "r"(s1[3]) : "memory");
    };

    auto b_copy = [&](int buf, int t) {
        cp_async16(BOFF(buf, 0) + b_dst, bsrc0 + t * BK);
        cp_async16(BOFF(buf, 1) + b_dst, bsrc1 + t * BK);
        asm volatile("cp.async.commit_group;" ::: "memory");
    };

    // prologue: tile 0
    split_store(0);
    b_copy(0, 0);
    xr[0] = *(const float4*)(xptr + BK);
    xr[1] = *(const float4*)(xptr + BK + 4);

#pragma unroll 1
    for (int t = 0; t < NT; t++) {
        const int buf = t & 1;
        if (t + 1 < NT) {
            split_store(buf ^ 1);
            b_copy(buf ^ 1, t + 1);
            asm volatile("cp.async.wait_group 1;" ::: "memory");
        } else {
            asm volatile("cp.async.wait_group 0;" ::: "memory");
        }
        __syncthreads();

        if (t + 2 < NT) {
            const float* nx = xptr + (t + 2) * BK;
            xr[0] = *(const float4*)(nx);
            xr[1] = *(const float4*)(nx + 4);
        }

#pragma unroll
        for (int kk = 0; kk < 2; kk++) {
            uint32_t a0[4], a1[4], b0[2][4], b1[2][4];
            ldsm4(a0, AOFF(buf, 0) + (wm0 + arow_l) * ROWB + kk * 32 + akb);
            ldsm4(a1, AOFF(buf, 1) + (wm0 + arow_l) * ROWB + kk * 32 + akb);
#pragma unroll
            for (int h = 0; h < 2; h++) {
                ldsm4(b0[h], BOFF(buf, 0) + (wn0 + h * 16 + brow_l) * ROWB + kk * 32 + bkb);
                ldsm4(b1[h], BOFF(buf, 1) + (wn0 + h * 16 + brow_l) * ROWB + kk * 32 + bkb);
            }
#pragma unroll
            for (int nt = 0; nt < 4; nt++) {
                mma16816(accM[nt], a0, &b0[nt >> 1][(nt & 1) * 2]);   // main
                mma16816(accC[nt], a0, &b1[nt >> 1][(nt & 1) * 2]);   // x0*w1'  (2^10 x)
                mma16816(accC[nt], a1, &b0[nt >> 1][(nt & 1) * 2]);   // x1'*w0  (2^10 x)
            }
        }

        // chunk flush into dedicated total accT (keeps main rounding walk short)
        if ((t & 15) == 15) {
#pragma unroll
            for (int nt = 0; nt < 4; nt++)
#pragma unroll
                for (int r = 0; r < 4; r++) {
                    accT[nt][r] += accM[nt][r];
                    accM[nt][r] = 0.0f;
                }
        }
        __syncthreads();
    }

    // ---------------- epilogue ----------------
    float* ScA = (float*)(dsm + (SA - smem_u32(dsm)));   // reuse tile smem
#pragma unroll
    for (int nt = 0; nt < 4; nt++)
#pragma unroll
        for (int h = 0; h < 2; h++) {
            int m = wm0 + h * 8 + (lane >> 2);
            int n = wn0 + nt * 8 + (lane & 3) * 2;
            float l0 = fmaf(accC[nt][2*h],   RSCALE_INV, accT[nt][2*h]);
            float l1 = fmaf(accC[nt][2*h+1], RSCALE_INV, accT[nt][2*h+1]);
            float v0 = 1.0f / (1.0f + expf(-l0));
            float v1 = 1.0f / (1.0f + expf(-l1));
            ScA[m * 65 + n]     = v0;
            ScA[m * 65 + n + 1] = v1;
            *(float2*)&out[OFF_SC + (size_t)(m0 + m) * NEXP + n] = make_float2(v0, v1);
        }
    __syncthreads();

    // per-token top-8 (threads 0..63), strict > scan => lowest index wins ties
    if (tid < 64) {
        const int tok = m0 + tid;
        const float* row = &ScA[tid * 65];
        unsigned long long used = 0ULL;
        float ps[TOPK]; int pidx[TOPK];
        float ssum = 0.0f;
        for (int k = 0; k < TOPK; k++) {
            float best = -INFINITY, bsc = 0.0f;
            int bi = 0;
#pragma unroll
            for (int e = 0; e < NEXP; e++) {
                float v = row[e] + sbias[e];
                if (!((used >> e) & 1ULL) && v > best) { best = v; bi = e; bsc = row[e]; }
            }
            used |= (1ULL << bi);
            ps[k] = bsc; pidx[k] = bi; ssum += bsc;
            atomicAdd(&shist[bi], 1.0f);
        }
        float inv = 1.0f / (ssum + 1e-20f);
        float ent = 0.0f;
#pragma unroll
        for (int k = 0; k < TOPK; k++) {
            float p = ps[k] * inv;             // ROUTE_SCALE == 1.0
            out[OFF_TOP + (size_t)tok * TOPK + k] = p;
            out[OFF_IDX + (size_t)tok * TOPK + k] = (float)pidx[k];
            ent += p * logf(p);
        }
        atomicAdd(&out[OFF_ENT], -ent * (1.0f / (float)NTOK));
    }
    __syncthreads();
    if (tid < NEXP) {
        float h = shist[tid];
        if (h != 0.0f) atomicAdd(&out[OFF_HIST + tid], h);
    }
}

extern "C" void kernel_launch(void* const* d_in, const int* in_sizes, int n_in,
                              void* d_out, int out_size) {
    const float* x    = (const float*)d_in[0];
    const float* W    = (const float*)d_in[1];
    const float* bias = (const float*)d_in[2];
    float* out = (float*)d_out;

    cudaFuncSetAttribute(router_mma_kernel,
                         cudaFuncAttributeMaxDynamicSharedMemorySize, DSMEM_BYTES);
    wconv_kernel<<<NEXP, 256>>>(W, out);
    router_mma_kernel<<<NTOK / BM, THREADS, DSMEM_BYTES>>>(x, bias, out);
}